// round 11
// baseline (speedup 1.0000x reference)
#include <cuda_runtime.h>
#include <cuda_fp16.h>
#include <cstdint>

// ---------------------------------------------------------------------------
// Problem constants
// ---------------------------------------------------------------------------
#define IN_F    4096
#define OUT_F   16384
#define ACT_IN  2048
#define ACT_OUT 8192
#define NROWS   8192      // B*S

// GEMM tiling: CTA 256(M) x 128(N), 16 warps as 4(M) x 4(N), warp tile 64x32
#define BM 256
#define BN 128
#define KC 64                    // K elements per stage (128 B/row in smem)
#define NSTAGE (ACT_IN / KC)     // 32
#define NTH 512
#define NBUF 4                   // cp.async pipeline depth

// SMEM per stage: A 32K | B 16K = 48 KB; 4 stages = 192 KB
#define T_A 0
#define T_B 32768
#define STAGE_BYTES 49152
#define SMEM_TOTAL  (NBUF * STAGE_BYTES)   // 196608

// fp16 operand scratch (allocation-free rule: __device__ globals).
// Both operands rounded once to fp16; measured rel_err 2.93e-4 << 1e-3 gate.
__device__ __half g_A[(size_t)NROWS * ACT_IN];
__device__ __half g_B[(size_t)ACT_OUT * ACT_IN];

// ---------------------------------------------------------------------------
// PTX helpers (sm_80-baseline only — harness lowers through plain compute_103)
// ---------------------------------------------------------------------------
__device__ __forceinline__ uint32_t smem_u32(const void* p) {
    uint32_t a;
    asm("{ .reg .u64 t; cvta.to.shared.u64 t, %1; cvt.u32.u64 %0, t; }"
        : "=r"(a) : "l"(p));
    return a;
}

#define SWZ(o) ((o) ^ (((o) >> 3) & 0x70))   // SW128 xor swizzle (16B granules)

#define CPA16(sa, gp) \
    asm volatile("cp.async.cg.shared.global [%0], [%1], 16;" :: "r"(sa), "l"(gp) : "memory")
#define CPA_COMMIT() asm volatile("cp.async.commit_group;" ::: "memory")
#define CPA_WAIT(n)  asm volatile("cp.async.wait_group %0;" :: "n"(n) : "memory")

#define LDSM4(r0, r1, r2, r3, a) \
    asm volatile("ldmatrix.sync.aligned.m8n8.x4.shared.b16 {%0,%1,%2,%3}, [%4];" \
                 : "=r"(r0), "=r"(r1), "=r"(r2), "=r"(r3) : "r"(a))

// D += A*B, fp16 in, fp32 accum.  A frag 4xb32, B frag 2xb32, C 4xf32.
#define MMA(c, a0, a1, a2, a3, b0, b1) \
    asm volatile("mma.sync.aligned.m16n8k16.row.col.f32.f16.f16.f32 " \
                 "{%0,%1,%2,%3}, {%4,%5,%6,%7}, {%8,%9}, {%0,%1,%2,%3};" \
                 : "+f"((c)[0]), "+f"((c)[1]), "+f"((c)[2]), "+f"((c)[3]) \
                 : "r"(a0), "r"(a1), "r"(a2), "r"(a3), "r"(b0), "r"(b1))

// ---------------------------------------------------------------------------
// Pre-pass 1: gather active cols -> fp16, AND zero the output buffer
// (fused: each of the 16M threads also writes 32 B of zeros, coalesced).
// ---------------------------------------------------------------------------
__global__ void nsl_gather_x(const float* __restrict__ x,
                             const int* __restrict__ in_idx,
                             float4* __restrict__ outv) {
    const int k = blockIdx.x * blockDim.x + threadIdx.x;
    const int m = blockIdx.y;
    const int c = __ldg(&in_idx[k]);
    g_A[(size_t)m * ACT_IN + k] = __float2half_rn(__ldg(&x[(size_t)m * IN_F + c]));

    // zero 8 floats (2 float4) of out: total 16M threads * 32B = 512 MB exactly
    const size_t gid = ((size_t)blockIdx.y * gridDim.x + blockIdx.x) * blockDim.x
                       + threadIdx.x;
    const float4 z = {0.f, 0.f, 0.f, 0.f};
    outv[gid * 2 + 0] = z;
    outv[gid * 2 + 1] = z;
}

// Pre-pass 2: round weight fp32 -> fp16
__global__ void nsl_round_w(const float* __restrict__ w) {
    const size_t i = blockIdx.x * (size_t)blockDim.x + threadIdx.x;
    g_B[i] = __float2half_rn(__ldg(&w[i]));
}

// ---------------------------------------------------------------------------
// Main GEMM: C[m, out_idx[n]] = sum_k A[m,k]*B[n,k] + bias[n]
// Single fp16 HMMA product, fp32 register accumulation, 4-stage pipeline,
// 16 warps (4 per SMSP) for LDSM->MMA latency hiding.
// ---------------------------------------------------------------------------
__global__ __launch_bounds__(NTH, 1)
void nsl_mma(const float* __restrict__ bias,
             const int*   __restrict__ out_idx,
             float*       __restrict__ out) {
    extern __shared__ __align__(1024) char smem[];
    const uint32_t sb = smem_u32(smem);
    const int tid  = threadIdx.x;
    const int wid  = tid >> 5;
    const int lane = tid & 31;
    const int m0 = blockIdx.y * BM;
    const int n0 = blockIdx.x * BN;

    const int warp_m = wid >> 2;       // 0..3  -> 64-row slab of M
    const int warp_n = wid & 3;        // 0..3  -> 32-col slab of N

    // ---- cp.async slot mapping ----
    // A tile: 256 rows x 8 x 16B = 2048 chunks -> 4/thread
    // B tile: 128 rows x 8 x 16B = 1024 chunks -> 2/thread
    int aG[4]; uint32_t aS[4];
    int bG[2]; uint32_t bS[2];
#pragma unroll
    for (int i = 0; i < 4; i++) {
        const int id = tid + i * NTH;
        const int r = id >> 3, cv = id & 7;
        aG[i] = r * ACT_IN + cv * 8;
        aS[i] = SWZ((uint32_t)(r * 128 + cv * 16));
    }
#pragma unroll
    for (int i = 0; i < 2; i++) {
        const int id = tid + i * NTH;
        const int r = id >> 3, cv = id & 7;
        bG[i] = r * ACT_IN + cv * 8;
        bS[i] = SWZ((uint32_t)(r * 128 + cv * 16));
    }
    const __half* pA = g_A + (size_t)m0 * ACT_IN;
    const __half* pB = g_B + (size_t)n0 * ACT_IN;

    auto load_stage = [&](int s) {
        const uint32_t base = sb + (s & (NBUF - 1)) * STAGE_BYTES;
        const int ke = s * KC;
#pragma unroll
        for (int i = 0; i < 4; i++)
            CPA16(base + T_A + aS[i], pA + ke + aG[i]);
#pragma unroll
        for (int i = 0; i < 2; i++)
            CPA16(base + T_B + bS[i], pB + ke + bG[i]);
        CPA_COMMIT();
    };

    // ---- ldmatrix lane addressing ----
    // SWZ(row*128 + kb) = row*128 + (((row&7)<<4) ^ kb) for kb < 128.
    const int lrow  = lane & 15;
    const uint32_t lkoff = (uint32_t)((lane >> 4) * 16);

    uint32_t aBase[4];
#pragma unroll
    for (int mt = 0; mt < 4; mt++) {
        const int row = warp_m * 64 + mt * 16 + lrow;
        aBase[mt] = (uint32_t)(row * 128) + (((uint32_t)(row & 7)) << 4);
    }
    uint32_t bBase[2];
#pragma unroll
    for (int g = 0; g < 2; g++) {
        const int row = warp_n * 32 + g * 16 + lrow;
        bBase[g] = (uint32_t)(row * 128) + (((uint32_t)(row & 7)) << 4);
    }

    // ---- accumulators: 4 m-tiles x 4 n8-tiles x 4 f32 = 64 regs ----
    float acc[4][4][4];
#pragma unroll
    for (int i = 0; i < 4; i++)
#pragma unroll
        for (int j = 0; j < 4; j++)
#pragma unroll
            for (int q = 0; q < 4; q++) acc[i][j][q] = 0.0f;

    // ---- prologue: 3 stages in flight ----
    load_stage(0);
    load_stage(1);
    load_stage(2);

    for (int s = 0; s < NSTAGE; s++) {
        CPA_WAIT(2);          // pending {s, s+1, s+2} -> group s complete
        __syncthreads();      // fences compute s-1 (last reader of buf (s+3)%4)

        if (s + 3 < NSTAGE) load_stage(s + 3);   // refills buf (s-1)%4

        const uint32_t base = sb + (s & (NBUF - 1)) * STAGE_BYTES;

#pragma unroll
        for (int ks = 0; ks < 4; ks++) {
            const uint32_t kb = (uint32_t)(ks * 32) + lkoff;

            // A fragments for this k16: 4 m-tiles (16 regs)
            uint32_t ah[4][4];
#pragma unroll
            for (int mt = 0; mt < 4; mt++)
                LDSM4(ah[mt][0], ah[mt][1], ah[mt][2], ah[mt][3],
                      base + T_A + (aBase[mt] ^ kb));

            // B in 2 groups of n16 (4 transient regs each)
#pragma unroll
            for (int g = 0; g < 2; g++) {
                uint32_t b0, b1, b2, b3;
                LDSM4(b0, b1, b2, b3, base + T_B + (bBase[g] ^ kb));
#pragma unroll
                for (int mt = 0; mt < 4; mt++) {
                    MMA(acc[mt][2*g+0], ah[mt][0], ah[mt][1], ah[mt][2], ah[mt][3], b0, b2);
                    MMA(acc[mt][2*g+1], ah[mt][0], ah[mt][1], ah[mt][2], ah[mt][3], b1, b3);
                }
            }
        }
    }

    // ---- epilogue: bias + scatter straight from C fragments ----
    const int trow = lane >> 2;
    const int tcol = (lane & 3) * 2;
    int   oc0[4], oc1[4];
    float bv0[4], bv1[4];
#pragma unroll
    for (int nt = 0; nt < 4; nt++) {
        const int n = n0 + warp_n * 32 + nt * 8 + tcol;
        oc0[nt] = __ldg(&out_idx[n]);     oc1[nt] = __ldg(&out_idx[n + 1]);
        bv0[nt] = __ldg(&bias[n]);        bv1[nt] = __ldg(&bias[n + 1]);
    }
#pragma unroll
    for (int mt = 0; mt < 4; mt++) {
        const int m = m0 + warp_m * 64 + mt * 16 + trow;
        float* r0 = out + (size_t)m * OUT_F;
        float* r1 = out + (size_t)(m + 8) * OUT_F;
#pragma unroll
        for (int nt = 0; nt < 4; nt++) {
            r0[oc0[nt]] = acc[mt][nt][0] + bv0[nt];
            r0[oc1[nt]] = acc[mt][nt][1] + bv1[nt];
            r1[oc0[nt]] = acc[mt][nt][2] + bv0[nt];
            r1[oc1[nt]] = acc[mt][nt][3] + bv1[nt];
        }
    }
}

// ---------------------------------------------------------------------------
// Launch
// ---------------------------------------------------------------------------
extern "C" void kernel_launch(void* const* d_in, const int* in_sizes, int n_in,
                              void* d_out, int out_size) {
    const float* x       = (const float*)d_in[0];
    const float* weight  = (const float*)d_in[1];
    const float* bias    = (const float*)d_in[2];
    const int*   in_idx  = (const int*)d_in[3];
    const int*   out_idx = (const int*)d_in[4];
    float* out = (float*)d_out;

    // pre-pass: gather+round A, zero output (fused), round B
    {
        dim3 g(ACT_IN / 256, NROWS);
        nsl_gather_x<<<g, 256>>>(x, in_idx, (float4*)out);
    }
    nsl_round_w<<<(ACT_OUT * ACT_IN) / 256, 256>>>(weight);

    // tensor-core GEMM (mma.sync) + bias + scatter
    cudaFuncSetAttribute(nsl_mma, cudaFuncAttributeMaxDynamicSharedMemorySize,
                         SMEM_TOTAL);
    dim3 grid(ACT_OUT / BN, NROWS / BM);   // 64 x 32
    nsl_mma<<<grid, NTH, SMEM_TOTAL>>>(bias, out_idx, out);
}

// round 12
// speedup vs baseline: 1.0112x; 1.0112x over previous
#include <cuda_runtime.h>
#include <cuda_fp16.h>
#include <cstdint>

// ---------------------------------------------------------------------------
// Problem constants
// ---------------------------------------------------------------------------
#define IN_F    4096
#define OUT_F   16384
#define ACT_IN  2048
#define ACT_OUT 8192
#define NROWS   8192      // B*S

// GEMM tiling: CTA 256(M) x 128(N), 8 warps as 4(M) x 2(N), warp tile 64x64
#define BM 256
#define BN 128
#define KC 64                    // K elements per stage (128 B/row in smem)
#define NSTAGE (ACT_IN / KC)     // 32
#define NTH 256
#define NBUF 4                   // cp.async pipeline depth

// SMEM per stage: A 32K | B 16K = 48 KB; 4 stages = 192 KB
#define T_A 0
#define T_B 32768
#define STAGE_BYTES 49152
#define SMEM_TOTAL  (NBUF * STAGE_BYTES)   // 196608

// fp16 operand scratch (allocation-free rule: __device__ globals).
// Both operands rounded once to fp16; measured rel_err 2.93e-4 << 1e-3 gate.
__device__ __half g_A[(size_t)NROWS * ACT_IN];
__device__ __half g_B[(size_t)ACT_OUT * ACT_IN];

// ---------------------------------------------------------------------------
// PTX helpers (sm_80-baseline only — harness lowers through plain compute_103)
// ---------------------------------------------------------------------------
__device__ __forceinline__ uint32_t smem_u32(const void* p) {
    uint32_t a;
    asm("{ .reg .u64 t; cvta.to.shared.u64 t, %1; cvt.u32.u64 %0, t; }"
        : "=r"(a) : "l"(p));
    return a;
}

#define SWZ(o) ((o) ^ (((o) >> 3) & 0x70))   // SW128 xor swizzle (16B granules)

#define CPA16(sa, gp) \
    asm volatile("cp.async.cg.shared.global [%0], [%1], 16;" :: "r"(sa), "l"(gp) : "memory")
#define CPA_COMMIT() asm volatile("cp.async.commit_group;" ::: "memory")
#define CPA_WAIT(n)  asm volatile("cp.async.wait_group %0;" :: "n"(n) : "memory")

#define LDSM4(r0, r1, r2, r3, a) \
    asm volatile("ldmatrix.sync.aligned.m8n8.x4.shared.b16 {%0,%1,%2,%3}, [%4];" \
                 : "=r"(r0), "=r"(r1), "=r"(r2), "=r"(r3) : "r"(a))

// D += A*B, fp16 in, fp32 accum.  A frag 4xb32, B frag 2xb32, C 4xf32.
#define MMA(c, a0, a1, a2, a3, b0, b1) \
    asm volatile("mma.sync.aligned.m16n8k16.row.col.f32.f16.f16.f32 " \
                 "{%0,%1,%2,%3}, {%4,%5,%6,%7}, {%8,%9}, {%0,%1,%2,%3};" \
                 : "+f"((c)[0]), "+f"((c)[1]), "+f"((c)[2]), "+f"((c)[3]) \
                 : "r"(a0), "r"(a1), "r"(a2), "r"(a3), "r"(b0), "r"(b1))

// ---------------------------------------------------------------------------
// Pre-pass 1: gather active cols -> fp16, AND zero the output buffer
// (fused: each of the 16M threads also writes 32 B of zeros, coalesced).
// ---------------------------------------------------------------------------
__global__ void nsl_gather_x(const float* __restrict__ x,
                             const int* __restrict__ in_idx,
                             float4* __restrict__ outv) {
    const int k = blockIdx.x * blockDim.x + threadIdx.x;
    const int m = blockIdx.y;
    const int c = __ldg(&in_idx[k]);
    g_A[(size_t)m * ACT_IN + k] = __float2half_rn(__ldg(&x[(size_t)m * IN_F + c]));

    // zero 8 floats (2 float4) of out: total 16M threads * 32B = 512 MB exactly
    const size_t gid = ((size_t)blockIdx.y * gridDim.x + blockIdx.x) * blockDim.x
                       + threadIdx.x;
    const float4 z = {0.f, 0.f, 0.f, 0.f};
    outv[gid * 2 + 0] = z;
    outv[gid * 2 + 1] = z;
}

// Pre-pass 2: round weight fp32 -> fp16
__global__ void nsl_round_w(const float* __restrict__ w) {
    const size_t i = blockIdx.x * (size_t)blockDim.x + threadIdx.x;
    g_B[i] = __float2half_rn(__ldg(&w[i]));
}

// ---------------------------------------------------------------------------
// Main GEMM: C[m, out_idx[n]] = sum_k A[m,k]*B[n,k] + bias[n]
// Single fp16 HMMA product, fp32 register accumulation, 4-stage cp.async
// pipeline, software-pipelined LDSM rotation (fragments prefetched one
// group ahead of their consuming MMAs).
// ---------------------------------------------------------------------------
__global__ __launch_bounds__(NTH, 1)
void nsl_mma(const float* __restrict__ bias,
             const int*   __restrict__ out_idx,
             float*       __restrict__ out) {
    extern __shared__ __align__(1024) char smem[];
    const uint32_t sb = smem_u32(smem);
    const int tid  = threadIdx.x;
    const int wid  = tid >> 5;
    const int lane = tid & 31;
    const int m0 = blockIdx.y * BM;
    const int n0 = blockIdx.x * BN;

    const int warp_m = wid >> 1;       // 0..3  -> 64-row slab of M
    const int warp_n = wid & 1;        // 0..1  -> 64-col slab of N

    // ---- cp.async slot mapping ----
    int aG[8]; uint32_t aS[8];
    int bG[4]; uint32_t bS[4];
#pragma unroll
    for (int i = 0; i < 8; i++) {
        const int id = tid + i * NTH;
        const int r = id >> 3, cv = id & 7;
        aG[i] = r * ACT_IN + cv * 8;
        aS[i] = SWZ((uint32_t)(r * 128 + cv * 16));
    }
#pragma unroll
    for (int i = 0; i < 4; i++) {
        const int id = tid + i * NTH;
        const int r = id >> 3, cv = id & 7;
        bG[i] = r * ACT_IN + cv * 8;
        bS[i] = SWZ((uint32_t)(r * 128 + cv * 16));
    }
    const __half* pA = g_A + (size_t)m0 * ACT_IN;
    const __half* pB = g_B + (size_t)n0 * ACT_IN;

    auto load_stage = [&](int s) {
        const uint32_t base = sb + (s & (NBUF - 1)) * STAGE_BYTES;
        const int ke = s * KC;
#pragma unroll
        for (int i = 0; i < 8; i++)
            CPA16(base + T_A + aS[i], pA + ke + aG[i]);
#pragma unroll
        for (int i = 0; i < 4; i++)
            CPA16(base + T_B + bS[i], pB + ke + bG[i]);
        CPA_COMMIT();
    };

    // ---- ldmatrix lane addressing ----
    // SWZ(row*128 + kb) = row*128 + (((row&7)<<4) ^ kb) for kb < 128.
    const int lrow  = lane & 15;
    const uint32_t lkoff = (uint32_t)((lane >> 4) * 16);

    uint32_t aBase[4];
#pragma unroll
    for (int mt = 0; mt < 4; mt++) {
        const int row = warp_m * 64 + mt * 16 + lrow;
        aBase[mt] = (uint32_t)(row * 128) + (((uint32_t)(row & 7)) << 4);
    }
    uint32_t bBase[4];
#pragma unroll
    for (int g = 0; g < 4; g++) {
        const int row = warp_n * 64 + g * 16 + lrow;
        bBase[g] = (uint32_t)(row * 128) + (((uint32_t)(row & 7)) << 4);
    }

    // ---- accumulators: 4 m-tiles x 8 n8-tiles x 4 f32 = 128 regs ----
    float acc[4][8][4];
#pragma unroll
    for (int i = 0; i < 4; i++)
#pragma unroll
        for (int j = 0; j < 8; j++)
#pragma unroll
            for (int q = 0; q < 4; q++) acc[i][j][q] = 0.0f;

    // fragment rotation buffers: A double-buffered by ks parity, B by group parity
    uint32_t aF[2][4][4];
    uint32_t bF[2][4];

    // ---- prologue: 3 stages in flight ----
    load_stage(0);
    load_stage(1);
    load_stage(2);

    for (int s = 0; s < NSTAGE; s++) {
        CPA_WAIT(2);          // pending {s, s+1, s+2} -> group s complete
        __syncthreads();      // fences compute s-1 (last reader of buf (s+3)%4)

        if (s + 3 < NSTAGE) load_stage(s + 3);   // refills buf (s-1)%4

        const uint32_t base = sb + (s & (NBUF - 1)) * STAGE_BYTES;

        // stage preamble: first A-quad + first B group (the only exposed LDSMs)
#pragma unroll
        for (int mt = 0; mt < 4; mt++)
            LDSM4(aF[0][mt][0], aF[0][mt][1], aF[0][mt][2], aF[0][mt][3],
                  base + T_A + (aBase[mt] ^ lkoff));
        LDSM4(bF[0][0], bF[0][1], bF[0][2], bF[0][3],
              base + T_B + (bBase[0] ^ lkoff));

#pragma unroll
        for (int ks = 0; ks < 4; ks++) {
            const uint32_t kb  = (uint32_t)(ks * 32) + lkoff;
            const uint32_t kbn = (uint32_t)((ks + 1) * 32) + lkoff;
            const int kc = ks & 1;          // current A buffer

#pragma unroll
            for (int g = 0; g < 4; g++) {
                // prefetch one step ahead of the MMAs below
                if (g < 3) {
                    LDSM4(bF[(g + 1) & 1][0], bF[(g + 1) & 1][1],
                          bF[(g + 1) & 1][2], bF[(g + 1) & 1][3],
                          base + T_B + (bBase[g + 1] ^ kb));
                } else if (ks < 3) {
#pragma unroll
                    for (int mt = 0; mt < 4; mt++)
                        LDSM4(aF[kc ^ 1][mt][0], aF[kc ^ 1][mt][1],
                              aF[kc ^ 1][mt][2], aF[kc ^ 1][mt][3],
                              base + T_A + (aBase[mt] ^ kbn));
                    LDSM4(bF[0][0], bF[0][1], bF[0][2], bF[0][3],
                          base + T_B + (bBase[0] ^ kbn));
                }

                const int gb = g & 1;       // current B buffer
#pragma unroll
                for (int mt = 0; mt < 4; mt++) {
                    MMA(acc[mt][2*g+0], aF[kc][mt][0], aF[kc][mt][1],
                        aF[kc][mt][2], aF[kc][mt][3], bF[gb][0], bF[gb][2]);
                    MMA(acc[mt][2*g+1], aF[kc][mt][0], aF[kc][mt][1],
                        aF[kc][mt][2], aF[kc][mt][3], bF[gb][1], bF[gb][3]);
                }
            }
        }
    }

    // ---- epilogue: bias + scatter straight from C fragments ----
    const int trow = lane >> 2;
    const int tcol = (lane & 3) * 2;
    int   oc0[8], oc1[8];
    float bv0[8], bv1[8];
#pragma unroll
    for (int nt = 0; nt < 8; nt++) {
        const int n = n0 + warp_n * 64 + nt * 8 + tcol;
        oc0[nt] = __ldg(&out_idx[n]);     oc1[nt] = __ldg(&out_idx[n + 1]);
        bv0[nt] = __ldg(&bias[n]);        bv1[nt] = __ldg(&bias[n + 1]);
    }
#pragma unroll
    for (int mt = 0; mt < 4; mt++) {
        const int m = m0 + warp_m * 64 + mt * 16 + trow;
        float* r0 = out + (size_t)m * OUT_F;
        float* r1 = out + (size_t)(m + 8) * OUT_F;
#pragma unroll
        for (int nt = 0; nt < 8; nt++) {
            r0[oc0[nt]] = acc[mt][nt][0] + bv0[nt];
            r0[oc1[nt]] = acc[mt][nt][1] + bv1[nt];
            r1[oc0[nt]] = acc[mt][nt][2] + bv0[nt];
            r1[oc1[nt]] = acc[mt][nt][3] + bv1[nt];
        }
    }
}

// ---------------------------------------------------------------------------
// Launch
// ---------------------------------------------------------------------------
extern "C" void kernel_launch(void* const* d_in, const int* in_sizes, int n_in,
                              void* d_out, int out_size) {
    const float* x       = (const float*)d_in[0];
    const float* weight  = (const float*)d_in[1];
    const float* bias    = (const float*)d_in[2];
    const int*   in_idx  = (const int*)d_in[3];
    const int*   out_idx = (const int*)d_in[4];
    float* out = (float*)d_out;

    // pre-pass: gather+round A, zero output (fused), round B
    {
        dim3 g(ACT_IN / 256, NROWS);
        nsl_gather_x<<<g, 256>>>(x, in_idx, (float4*)out);
    }
    nsl_round_w<<<(ACT_OUT * ACT_IN) / 256, 256>>>(weight);

    // tensor-core GEMM (mma.sync) + bias + scatter
    cudaFuncSetAttribute(nsl_mma, cudaFuncAttributeMaxDynamicSharedMemorySize,
                         SMEM_TOTAL);
    dim3 grid(ACT_OUT / BN, NROWS / BM);   // 64 x 32
    nsl_mma<<<grid, NTH, SMEM_TOTAL>>>(bias, out_idx, out);
}